// round 15
// baseline (speedup 1.0000x reference)
#include <cuda_runtime.h>
#include <cuda_fp16.h>
#include <math.h>
#include <stdint.h>

// Problem constants
#define BATCH 16
#define SEQ   1024
#define CDIM  768
#define HEADS 12
#define HDIM  64
#define QKVC  2304
#define MROWS 16384

// ---------------------------------------------------------------------------
// Scratch (__device__ globals; allocation-free rule)
// ---------------------------------------------------------------------------
#define HELEMS ((size_t)BATCH * HEADS * SEQ * HDIM)
__device__ __align__(128) __half g_x [(size_t)MROWS * CDIM];
__device__ __align__(128) __half g_wq[(size_t)QKVC  * CDIM];
__device__ __align__(128) __half g_wp[(size_t)CDIM  * CDIM];
__device__ __align__(128) __half g_q[HELEMS];
__device__ __align__(128) __half g_k[HELEMS];
__device__ __align__(128) __half g_v[HELEMS];
__device__ __align__(128) __half g_a[(size_t)MROWS * CDIM];

// ---------------------------------------------------------------------------
// PTX helpers
// ---------------------------------------------------------------------------
__device__ __forceinline__ uint32_t smem_u32(const void* p) {
    uint32_t a;
    asm("{ .reg .u64 t; cvta.to.shared.u64 t, %1; cvt.u32.u64 %0, t; }" : "=r"(a) : "l"(p));
    return a;
}
#define CP_ASYNC16(dst, src) \
    asm volatile("cp.async.cg.shared.global [%0], [%1], 16;" :: "r"(dst), "l"(src))
#define CP_COMMIT() asm volatile("cp.async.commit_group;" ::: "memory")
#define CP_WAIT(n)  asm volatile("cp.async.wait_group %0;" :: "n"(n) : "memory")

#define LDSM_X4(r0, r1, r2, r3, addr) \
    asm volatile("ldmatrix.sync.aligned.m8n8.x4.shared.b16 {%0,%1,%2,%3}, [%4];" \
        : "=r"(r0), "=r"(r1), "=r"(r2), "=r"(r3) : "r"(addr))
#define LDSM_X4_T(r0, r1, r2, r3, addr) \
    asm volatile("ldmatrix.sync.aligned.m8n8.x4.trans.shared.b16 {%0,%1,%2,%3}, [%4];" \
        : "=r"(r0), "=r"(r1), "=r"(r2), "=r"(r3) : "r"(addr))

// fp32-accumulate MMA (attention)
#define MMA_F16(d, a, b0r, b1r) \
    asm volatile("mma.sync.aligned.m16n8k16.row.col.f32.f16.f16.f32 " \
        "{%0,%1,%2,%3},{%4,%5,%6,%7},{%8,%9},{%0,%1,%2,%3};" \
        : "+f"((d)[0]), "+f"((d)[1]), "+f"((d)[2]), "+f"((d)[3]) \
        : "r"((a)[0]), "r"((a)[1]), "r"((a)[2]), "r"((a)[3]), "r"(b0r), "r"(b1r))

// fp16-accumulate MMA (GEMMs; chained max 2 before fp32 flush)
#define MMA_F16D(d, a, b0r, b1r) \
    asm volatile("mma.sync.aligned.m16n8k16.row.col.f16.f16.f16.f16 " \
        "{%0,%1},{%2,%3,%4,%5},{%6,%7},{%0,%1};" \
        : "+r"((d)[0]), "+r"((d)[1]) \
        : "r"((a)[0]), "r"((a)[1]), "r"((a)[2]), "r"((a)[3]), "r"(b0r), "r"(b1r))

__device__ __forceinline__ uint32_t pack2h(float a, float b) {
    __half2 h = __floats2half2_rn(a, b);
    return *(uint32_t*)&h;
}

// ---------------------------------------------------------------------------
// Fused conversion kernel (one launch: x->fp16 + both W transposes)
// ---------------------------------------------------------------------------
#define NB_X   (MROWS * CDIM / 4 / 256)                 // 12288
#define NB_WQ  ((QKVC / 32) * (CDIM / 32))              // 1728
#define NB_WP  ((CDIM / 32) * (CDIM / 32))              // 576

__global__ void __launch_bounds__(256)
convert_all_kernel(const float* __restrict__ x,
                   const float* __restrict__ Wq,
                   const float* __restrict__ Wp)
{
    const int bid = blockIdx.x;
    const int tid = threadIdx.x;

    if (bid < NB_X) {
        const int i = bid * 256 + tid;
        float4 v = ((const float4*)x)[i];
        uint2 o;
        o.x = pack2h(v.x, v.y);
        o.y = pack2h(v.z, v.w);
        ((uint2*)g_x)[i] = o;
        return;
    }

    __shared__ float tile[32][33];
    const float* W;
    __half* o;
    int Nd, tb;
    if (bid < NB_X + NB_WQ) { W = Wq; o = g_wq; Nd = QKVC; tb = bid - NB_X; }
    else                    { W = Wp; o = g_wp; Nd = CDIM; tb = bid - NB_X - NB_WQ; }
    const int ntile = Nd / 32;
    const int n0 = (tb % ntile) * 32;
    const int k0 = (tb / ntile) * 32;
    const int tx = tid & 31, ty = tid >> 5;

    #pragma unroll
    for (int j = 0; j < 4; j++)
        tile[ty + j * 8][tx] = W[(size_t)(k0 + ty + j * 8) * Nd + n0 + tx];
    __syncthreads();
    #pragma unroll
    for (int j = 0; j < 4; j++) {
        const int n = n0 + ty + j * 8;
        const int k = k0 + tx;
        o[(size_t)n * CDIM + k] = __float2half(tile[tx][ty + j * 8]);
    }
}

// ---------------------------------------------------------------------------
// HMMA GEMM, fp16-accumulate chained over 32-K chunks, fp32 register flush.
// 128x128 CTA tile, BK=32, 3-stage cp.async, 256 threads (8 warps, 64x32
// warp tile).
// ---------------------------------------------------------------------------
#define TILE32_B  8192
#define STAGE16_B (2 * TILE32_B)
#define GEMM_SMEM (3 * STAGE16_B)       // 49152

__device__ __forceinline__ uint32_t fold_off(int row, int c16) {
    return (uint32_t)((row & 63) * 128 + (((((row >> 6) << 2) + c16) ^ (row & 7)) << 4));
}

template<bool QKV>
__global__ void __launch_bounds__(256, 1)
gemm_hmma_kernel(const float* __restrict__ bias,
                 const float* __restrict__ zeta,
                 float* __restrict__ Cout)
{
    const int N = QKV ? QKVC : CDIM;
    const __half* A = QKV ? g_x  : g_a;
    const __half* B = QKV ? g_wq : g_wp;

    extern __shared__ char smem[];
    const uint32_t sb = smem_u32(smem);
    const int tid  = threadIdx.x;
    const int lane = tid & 31;
    const int wid  = tid >> 5;           // 0..7
    const int wm   = (wid >> 2) * 64;    // 0 / 64
    const int wn   = (wid & 3) * 32;     // 0/32/64/96
    const int m0   = blockIdx.y * 128;
    const int n0   = blockIdx.x * 128;

    const __half* gA = A + (size_t)m0 * CDIM;
    const __half* gB = B + (size_t)n0 * CDIM;

    uint32_t offA[4], offB[2];
    {
        const int r = lane & 15, c = lane >> 4;
        #pragma unroll
        for (int mt = 0; mt < 4; mt++) offA[mt] = fold_off(wm + mt * 16 + r, c);
        #pragma unroll
        for (int nt = 0; nt < 2; nt++) offB[nt] = TILE32_B + fold_off(wn + nt * 16 + r, c);
    }

    float acc[4][4][4];
    uint32_t acc16[4][4][2];
    #pragma unroll
    for (int a = 0; a < 4; a++)
        #pragma unroll
        for (int b = 0; b < 4; b++) {
            #pragma unroll
            for (int c = 0; c < 4; c++) acc[a][b][c] = 0.f;
            acc16[a][b][0] = 0u; acc16[a][b][1] = 0u;
        }

    const int nch = CDIM / 32;   // 24

    auto load_stage = [&](int chunk, int stage) {
        const int k0 = chunk * 32;
        const uint32_t baseA = sb + stage * STAGE16_B;
        #pragma unroll
        for (int j = 0; j < 2; j++) {
            const int i = tid + j * 256;     // 0..511
            const int r = i >> 2;
            const int c = i & 3;
            const uint32_t fo = fold_off(r, c);
            CP_ASYNC16(baseA + fo,            gA + (size_t)r * CDIM + k0 + c * 8);
            CP_ASYNC16(baseA + TILE32_B + fo, gB + (size_t)r * CDIM + k0 + c * 8);
        }
        CP_COMMIT();
    };

    load_stage(0, 0);
    load_stage(1, 1);

    #pragma unroll 1
    for (int ch = 0; ch < nch; ch++) {
        if (ch + 1 < nch) { CP_WAIT(1); }
        else              { CP_WAIT(0); }
        __syncthreads();
        if (ch + 2 < nch) load_stage(ch + 2, (ch + 2) % 3);

        const uint32_t st = sb + (ch % 3) * STAGE16_B;

        // 2 MMAs chained in fp16 accumulators...
        #pragma unroll
        for (int kb = 0; kb < 2; kb++) {
            const uint32_t x = (uint32_t)(kb << 5);
            uint32_t af[4][4];
            #pragma unroll
            for (int mt = 0; mt < 4; mt++)
                LDSM_X4(af[mt][0], af[mt][1], af[mt][2], af[mt][3], st + (offA[mt] ^ x));
            uint32_t bf[2][4];
            #pragma unroll
            for (int nt = 0; nt < 2; nt++)
                LDSM_X4(bf[nt][0], bf[nt][1], bf[nt][2], bf[nt][3], st + (offB[nt] ^ x));
            #pragma unroll
            for (int mt = 0; mt < 4; mt++)
                #pragma unroll
                for (int n8 = 0; n8 < 4; n8++) {
                    const int nt = n8 >> 1, s2 = n8 & 1;
                    MMA_F16D(acc16[mt][n8], af[mt], bf[nt][s2], bf[nt][s2 + 2]);
                }
        }
        // ...then flushed to fp32 (bounds fp16 rounding to 2 chained adds)
        #pragma unroll
        for (int mt = 0; mt < 4; mt++)
            #pragma unroll
            for (int n8 = 0; n8 < 4; n8++) {
                float2 flo = __half22float2(*(__half2*)&acc16[mt][n8][0]);
                float2 fhi = __half22float2(*(__half2*)&acc16[mt][n8][1]);
                acc[mt][n8][0] += flo.x; acc[mt][n8][1] += flo.y;
                acc[mt][n8][2] += fhi.x; acc[mt][n8][3] += fhi.y;
                acc16[mt][n8][0] = 0u;   acc16[mt][n8][1] = 0u;
            }
    }

    // Epilogue
    const int quad = lane >> 2;
    const int tq   = (lane & 3) * 2;
    #pragma unroll
    for (int mt = 0; mt < 4; mt++) {
        #pragma unroll
        for (int n8 = 0; n8 < 4; n8++) {
            const int col = n0 + wn + n8 * 8 + tq;
            const int row = m0 + wm + mt * 16 + quad;
            float b0 = bias[col], b1 = bias[col + 1];
            if (QKV) {
                const int tsel = col / CDIM;
                const int hd = col % CDIM;
                const int hh = hd >> 6, d = hd & 63;
                float z0 = zeta[hd], z1 = zeta[hd + 1];
                float v0 = (acc[mt][n8][0] + b0) * z0;
                float v1 = (acc[mt][n8][1] + b1) * z1;
                float v2 = (acc[mt][n8][2] + b0) * z0;
                float v3 = (acc[mt][n8][3] + b1) * z1;
                if (tsel == 0) { v0 *= 0.125f; v1 *= 0.125f; v2 *= 0.125f; v3 *= 0.125f; }
                __half* dst = (tsel == 0) ? g_q : (tsel == 1) ? g_k : g_v;
                const int b = row >> 10, n = row & 1023;
                const size_t idx = (((size_t)(b * HEADS + hh)) << 16) + (size_t)n * 64 + d;
                *(uint32_t*)(dst + idx)          = pack2h(v0, v1);
                *(uint32_t*)(dst + idx + 8 * 64) = pack2h(v2, v3);
            } else {
                float2 v0 = { acc[mt][n8][0] + b0, acc[mt][n8][1] + b1 };
                float2 v1 = { acc[mt][n8][2] + b0, acc[mt][n8][3] + b1 };
                *(float2*)(Cout + (size_t)row * N + col)       = v0;
                *(float2*)(Cout + (size_t)(row + 8) * N + col) = v1;
            }
        }
    }
}

// ---------------------------------------------------------------------------
// Flash attention on fp16 mma.sync, fp32 accumulate (unchanged from R14).
// 64 q-rows per CTA, 128 threads (4 warps x 16 rows), double-buffered K/V.
// ---------------------------------------------------------------------------
#define AT_Q_B    8192
#define AT_KV_B   8192
#define AT_STAGE  (2 * AT_KV_B)
#define AT_SMEM   (AT_Q_B + 2 * AT_STAGE + 1024)

__global__ void __launch_bounds__(128, 2)
attn_hmma_kernel(const unsigned char* __restrict__ mask)
{
    extern __shared__ char sm[];
    const uint32_t sb = smem_u32(sm);
    const uint32_t stage_s = sb + AT_Q_B;
    unsigned char* msk = (unsigned char*)(sm + AT_Q_B + 2 * AT_STAGE);

    const int tid = threadIdx.x, lane = tid & 31, wid = tid >> 5;
    const int qt = blockIdx.x, h = blockIdx.y, b = blockIdx.z;
    const int m0 = qt * 64;
    const size_t head_off = ((size_t)(b * HEADS + h)) << 16;

    auto load_kv = [&](int t, int s) {
        const uint32_t base = stage_s + s * AT_STAGE;
        const size_t ko = head_off + (size_t)(t * 64) * 64;
        #pragma unroll
        for (int j = 0; j < 4; j++) {
            const int i = tid + j * 128;
            const int r = i >> 3, c = i & 7;
            const uint32_t soff = base + r * 128 + ((c ^ (r & 7)) << 4);
            CP_ASYNC16(soff,           g_k + ko + (size_t)r * 64 + c * 8);
            CP_ASYNC16(soff + AT_KV_B, g_v + ko + (size_t)r * 64 + c * 8);
        }
        CP_COMMIT();
    };
    load_kv(0, 0);

    const uint32_t mw0 = ((const uint32_t*)(mask + b * SEQ))[tid];
    const uint32_t mw1 = ((const uint32_t*)(mask + b * SEQ))[tid + 128];
    ((uint32_t*)msk)[tid]       = mw0;
    ((uint32_t*)msk)[tid + 128] = mw1;

    {
        const __half* qs = g_q + head_off + (size_t)m0 * 64;
        #pragma unroll
        for (int j = 0; j < 4; j++) {
            const int i = tid + j * 128;
            const int r = i >> 3, c = i & 7;
            const uint32_t sw = r * 128 + ((c ^ (r & 7)) << 4);
            *(uint4*)(sm + sw) = *(const uint4*)(qs + (size_t)r * 64 + c * 8);
        }
    }
    const int anymask = __syncthreads_or((mw0 | mw1) != 0);

    uint32_t qf[4][4];
    #pragma unroll
    for (int kb = 0; kb < 4; kb++) {
        const int row = wid * 16 + (lane & 15);
        const int col = kb * 2 + (lane >> 4);
        const uint32_t off = row * 128 + ((col ^ (row & 7)) << 4);
        LDSM_X4(qf[kb][0], qf[kb][1], qf[kb][2], qf[kb][3], sb + off);
    }

    uint32_t offK[4], offV[4];
    {
        const int r = lane & 15, c = lane >> 4;
        #pragma unroll
        for (int kg = 0; kg < 4; kg++) {
            const int row = kg * 16 + r;
            offK[kg] = row * 128 + ((c ^ (row & 7)) << 4);
        }
        const int ttv = lane >> 3;
        const int key0 = (ttv & 1) * 8 + (lane & 7);
        #pragma unroll
        for (int g = 0; g < 4; g++) {
            const int cc = 2 * g + (ttv >> 1);
            offV[g] = AT_KV_B + key0 * 128 + ((cc ^ (key0 & 7)) << 4);
        }
    }

    float mr0 = -1e30f, mr1 = -1e30f, lr0 = 0.f, lr1 = 0.f;
    float oa[8][4];
    #pragma unroll
    for (int i = 0; i < 8; i++)
        #pragma unroll
        for (int j = 0; j < 4; j++) oa[i][j] = 0.f;

    #pragma unroll 1
    for (int t = 0; t < 16; t++) {
        CP_WAIT(0);
        __syncthreads();
        if (t < 15) load_kv(t + 1, (t + 1) & 1);
        const uint32_t st = stage_s + (t & 1) * AT_STAGE;

        float sa[8][4];
        #pragma unroll
        for (int i = 0; i < 8; i++)
            #pragma unroll
            for (int j = 0; j < 4; j++) sa[i][j] = 0.f;

        #pragma unroll
        for (int kb = 0; kb < 4; kb++) {
            const uint32_t x = (uint32_t)(kb << 5);
            uint32_t kf[4][4];
            #pragma unroll
            for (int kg = 0; kg < 4; kg++)
                LDSM_X4(kf[kg][0], kf[kg][1], kf[kg][2], kf[kg][3], st + (offK[kg] ^ x));
            #pragma unroll
            for (int kg = 0; kg < 4; kg++)
                #pragma unroll
                for (int s2 = 0; s2 < 2; s2++)
                    MMA_F16(sa[kg * 2 + s2], qf[kb], kf[kg][s2], kf[kg][s2 + 2]);
        }

        if (anymask) {
            #pragma unroll
            for (int n8 = 0; n8 < 8; n8++) {
                const int k0 = t * 64 + n8 * 8 + (lane & 3) * 2;
                if (msk[k0])     { sa[n8][0] = -3e30f; sa[n8][2] = -3e30f; }
                if (msk[k0 + 1]) { sa[n8][1] = -3e30f; sa[n8][3] = -3e30f; }
            }
        }

        {
            float t0 = sa[0][0], t1 = sa[0][2];
            #pragma unroll
            for (int n8 = 0; n8 < 8; n8++) {
                t0 = fmaxf(t0, fmaxf(sa[n8][0], sa[n8][1]));
                t1 = fmaxf(t1, fmaxf(sa[n8][2], sa[n8][3]));
            }
            t0 = fmaxf(t0, __shfl_xor_sync(0xFFFFFFFFu, t0, 1));
            t0 = fmaxf(t0, __shfl_xor_sync(0xFFFFFFFFu, t0, 2));
            t1 = fmaxf(t1, __shfl_xor_sync(0xFFFFFFFFu, t1, 1));
            t1 = fmaxf(t1, __shfl_xor_sync(0xFFFFFFFFu, t1, 2));
            const float mn0 = fmaxf(mr0, t0), mn1 = fmaxf(mr1, t1);
            const float c0 = __expf(mr0 - mn0), c1 = __expf(mr1 - mn1);
            lr0 *= c0; lr1 *= c1;
            mr0 = mn0; mr1 = mn1;

            #pragma unroll
            for (int n8 = 0; n8 < 8; n8++) {
                const float p0 = __expf(sa[n8][0] - mn0);
                const float p1 = __expf(sa[n8][1] - mn0);
                const float p2 = __expf(sa[n8][2] - mn1);
                const float p3 = __expf(sa[n8][3] - mn1);
                lr0 += p0 + p1; lr1 += p2 + p3;
                oa[n8][0] *= c0; oa[n8][1] *= c0;
                oa[n8][2] *= c1; oa[n8][3] *= c1;
                sa[n8][0] = p0; sa[n8][1] = p1;
                sa[n8][2] = p2; sa[n8][3] = p3;
            }
        }

        #pragma unroll
        for (int kb = 0; kb < 4; kb++) {
            uint32_t pf[4];
            pf[0] = pack2h(sa[2 * kb][0],     sa[2 * kb][1]);
            pf[1] = pack2h(sa[2 * kb][2],     sa[2 * kb][3]);
            pf[2] = pack2h(sa[2 * kb + 1][0], sa[2 * kb + 1][1]);
            pf[3] = pack2h(sa[2 * kb + 1][2], sa[2 * kb + 1][3]);

            uint32_t vf[4][4];
            #pragma unroll
            for (int g = 0; g < 4; g++)
                LDSM_X4_T(vf[g][0], vf[g][1], vf[g][2], vf[g][3],
                          st + offV[g] + kb * 2048);
            #pragma unroll
            for (int g = 0; g < 4; g++)
                #pragma unroll
                for (int s2 = 0; s2 < 2; s2++)
                    MMA_F16(oa[g * 2 + s2], pf, vf[g][2 * s2], vf[g][2 * s2 + 1]);
        }
    }

    lr0 += __shfl_xor_sync(0xFFFFFFFFu, lr0, 1);
    lr0 += __shfl_xor_sync(0xFFFFFFFFu, lr0, 2);
    lr1 += __shfl_xor_sync(0xFFFFFFFFu, lr1, 1);
    lr1 += __shfl_xor_sync(0xFFFFFFFFu, lr1, 2);
    const float inv0 = 1.f / lr0, inv1 = 1.f / lr1;

    const int r0 = m0 + wid * 16 + (lane >> 2);
    const int cb = h * 64 + (lane & 3) * 2;
    #pragma unroll
    for (int n8 = 0; n8 < 8; n8++) {
        const int col = cb + n8 * 8;
        const size_t i0 = (size_t)(b * SEQ + r0) * CDIM + col;
        const size_t i1 = i0 + (size_t)8 * CDIM;
        *(uint32_t*)(g_a + i0) = pack2h(oa[n8][0] * inv0, oa[n8][1] * inv0);
        *(uint32_t*)(g_a + i1) = pack2h(oa[n8][2] * inv1, oa[n8][3] * inv1);
    }
}

// ---------------------------------------------------------------------------
// Launch
// ---------------------------------------------------------------------------
extern "C" void kernel_launch(void* const* d_in, const int* in_sizes, int n_in,
                              void* d_out, int out_size)
{
    (void)in_sizes; (void)n_in; (void)out_size;
    const float* x      = (const float*)d_in[0];
    const float* W_qkv  = (const float*)d_in[1];
    const float* b_qkv  = (const float*)d_in[2];
    const float* zeta   = (const float*)d_in[3];
    const float* W_proj = (const float*)d_in[4];
    const float* b_proj = (const float*)d_in[5];
    const unsigned char* mask = (const unsigned char*)d_in[6];
    float* out = (float*)d_out;

    cudaFuncSetAttribute(gemm_hmma_kernel<true>,
                         cudaFuncAttributeMaxDynamicSharedMemorySize, GEMM_SMEM);
    cudaFuncSetAttribute(gemm_hmma_kernel<false>,
                         cudaFuncAttributeMaxDynamicSharedMemorySize, GEMM_SMEM);
    cudaFuncSetAttribute(attn_hmma_kernel,
                         cudaFuncAttributeMaxDynamicSharedMemorySize, AT_SMEM);

    convert_all_kernel<<<NB_X + NB_WQ + NB_WP, 256>>>(x, W_qkv, W_proj);
    gemm_hmma_kernel<true><<<dim3(QKVC / 128, MROWS / 128), 256, GEMM_SMEM>>>(b_qkv, zeta, nullptr);
    attn_hmma_kernel<<<dim3(SEQ / 64, HEADS, BATCH), 128, AT_SMEM>>>(mask);
    gemm_hmma_kernel<false><<<dim3(CDIM / 128, MROWS / 128), 256, GEMM_SMEM>>>(b_proj, nullptr, out);
}

// round 16
// speedup vs baseline: 1.1828x; 1.1828x over previous
#include <cuda_runtime.h>
#include <cuda_fp16.h>
#include <math.h>
#include <stdint.h>

// Problem constants
#define BATCH 16
#define SEQ   1024
#define CDIM  768
#define HEADS 12
#define HDIM  64
#define QKVC  2304
#define MROWS 16384

// ---------------------------------------------------------------------------
// Scratch (__device__ globals; allocation-free rule)
// ---------------------------------------------------------------------------
#define HELEMS ((size_t)BATCH * HEADS * SEQ * HDIM)
__device__ __align__(128) __half g_x [(size_t)MROWS * CDIM];
__device__ __align__(128) __half g_wq[(size_t)QKVC  * CDIM];
__device__ __align__(128) __half g_wp[(size_t)CDIM  * CDIM];
__device__ __align__(128) __half g_q[HELEMS];
__device__ __align__(128) __half g_k[HELEMS];
__device__ __align__(128) __half g_v[HELEMS];
__device__ __align__(128) __half g_a[(size_t)MROWS * CDIM];

// ---------------------------------------------------------------------------
// PTX helpers
// ---------------------------------------------------------------------------
__device__ __forceinline__ uint32_t smem_u32(const void* p) {
    uint32_t a;
    asm("{ .reg .u64 t; cvta.to.shared.u64 t, %1; cvt.u32.u64 %0, t; }" : "=r"(a) : "l"(p));
    return a;
}
#define CP_ASYNC16(dst, src) \
    asm volatile("cp.async.cg.shared.global [%0], [%1], 16;" :: "r"(dst), "l"(src))
#define CP_COMMIT() asm volatile("cp.async.commit_group;" ::: "memory")
#define CP_WAIT(n)  asm volatile("cp.async.wait_group %0;" :: "n"(n) : "memory")

#define LDSM_X4(r0, r1, r2, r3, addr) \
    asm volatile("ldmatrix.sync.aligned.m8n8.x4.shared.b16 {%0,%1,%2,%3}, [%4];" \
        : "=r"(r0), "=r"(r1), "=r"(r2), "=r"(r3) : "r"(addr))
#define LDSM_X4_T(r0, r1, r2, r3, addr) \
    asm volatile("ldmatrix.sync.aligned.m8n8.x4.trans.shared.b16 {%0,%1,%2,%3}, [%4];" \
        : "=r"(r0), "=r"(r1), "=r"(r2), "=r"(r3) : "r"(addr))

#define MMA_F16(d, a, b0r, b1r) \
    asm volatile("mma.sync.aligned.m16n8k16.row.col.f32.f16.f16.f32 " \
        "{%0,%1,%2,%3},{%4,%5,%6,%7},{%8,%9},{%0,%1,%2,%3};" \
        : "+f"((d)[0]), "+f"((d)[1]), "+f"((d)[2]), "+f"((d)[3]) \
        : "r"((a)[0]), "r"((a)[1]), "r"((a)[2]), "r"((a)[3]), "r"(b0r), "r"(b1r))

__device__ __forceinline__ uint32_t pack2h(float a, float b) {
    __half2 h = __floats2half2_rn(a, b);
    return *(uint32_t*)&h;
}

// ---------------------------------------------------------------------------
// Fused conversion kernel (one launch: x->fp16 + both W transposes)
// ---------------------------------------------------------------------------
#define NB_X   (MROWS * CDIM / 4 / 256)                 // 12288
#define NB_WQ  ((QKVC / 32) * (CDIM / 32))              // 1728
#define NB_WP  ((CDIM / 32) * (CDIM / 32))              // 576

__global__ void __launch_bounds__(256)
convert_all_kernel(const float* __restrict__ x,
                   const float* __restrict__ Wq,
                   const float* __restrict__ Wp)
{
    const int bid = blockIdx.x;
    const int tid = threadIdx.x;

    if (bid < NB_X) {
        const int i = bid * 256 + tid;
        float4 v = ((const float4*)x)[i];
        uint2 o;
        o.x = pack2h(v.x, v.y);
        o.y = pack2h(v.z, v.w);
        ((uint2*)g_x)[i] = o;
        return;
    }

    __shared__ float tile[32][33];
    const float* W;
    __half* o;
    int Nd, tb;
    if (bid < NB_X + NB_WQ) { W = Wq; o = g_wq; Nd = QKVC; tb = bid - NB_X; }
    else                    { W = Wp; o = g_wp; Nd = CDIM; tb = bid - NB_X - NB_WQ; }
    const int ntile = Nd / 32;
    const int n0 = (tb % ntile) * 32;
    const int k0 = (tb / ntile) * 32;
    const int tx = tid & 31, ty = tid >> 5;

    #pragma unroll
    for (int j = 0; j < 4; j++)
        tile[ty + j * 8][tx] = W[(size_t)(k0 + ty + j * 8) * Nd + n0 + tx];
    __syncthreads();
    #pragma unroll
    for (int j = 0; j < 4; j++) {
        const int n = n0 + ty + j * 8;
        const int k = k0 + tx;
        o[(size_t)n * CDIM + k] = __float2half(tile[tx][ty + j * 8]);
    }
}

// ---------------------------------------------------------------------------
// HMMA fp16 GEMM (fp32 accumulate, R13 config) — PERSISTENT tile loop.
// 128x128 CTA tile, BK=32, 3-stage cp.async, 128 threads (4 warps, 64x64).
// ---------------------------------------------------------------------------
#define TILE32_B  8192
#define STAGE16_B (2 * TILE32_B)
#define GEMM_SMEM (3 * STAGE16_B)       // 49152

__device__ __forceinline__ uint32_t fold_off(int row, int c16) {
    return (uint32_t)((row & 63) * 128 + (((((row >> 6) << 2) + c16) ^ (row & 7)) << 4));
}

template<bool QKV>
__global__ void __launch_bounds__(128, 2)
gemm_hmma_kernel(const float* __restrict__ bias,
                 const float* __restrict__ zeta,
                 float* __restrict__ Cout)
{
    const int N = QKV ? QKVC : CDIM;
    const int NTN = N / 128;                       // 18 or 6
    const int NTILES = NTN * (MROWS / 128);        // 2304 or 768
    const __half* A = QKV ? g_x  : g_a;
    const __half* B = QKV ? g_wq : g_wp;

    extern __shared__ char smem[];
    const uint32_t sb = smem_u32(smem);
    const int tid  = threadIdx.x;
    const int lane = tid & 31;
    const int wid  = tid >> 5;
    const int wm   = (wid >> 1) * 64;
    const int wn   = (wid & 1) * 64;

    uint32_t offA[4], offB[4];
    {
        const int r = lane & 15, c = lane >> 4;
        #pragma unroll
        for (int mt = 0; mt < 4; mt++) offA[mt] = fold_off(wm + mt * 16 + r, c);
        #pragma unroll
        for (int nt = 0; nt < 4; nt++) offB[nt] = TILE32_B + fold_off(wn + nt * 16 + r, c);
    }

    const int nch = CDIM / 32;   // 24

    #pragma unroll 1
    for (int tile = blockIdx.x; tile < NTILES; tile += gridDim.x) {
        const int m0 = (tile / NTN) * 128;
        const int n0 = (tile % NTN) * 128;
        const __half* gA = A + (size_t)m0 * CDIM;
        const __half* gB = B + (size_t)n0 * CDIM;

        float acc[4][8][4];
        #pragma unroll
        for (int a = 0; a < 4; a++)
            #pragma unroll
            for (int b = 0; b < 8; b++)
                #pragma unroll
                for (int c = 0; c < 4; c++) acc[a][b][c] = 0.f;

        auto load_stage = [&](int chunk, int stage) {
            const int k0 = chunk * 32;
            const uint32_t baseA = sb + stage * STAGE16_B;
            #pragma unroll
            for (int j = 0; j < 4; j++) {
                const int i = tid + j * 128;
                const int r = i >> 2;
                const int c = i & 3;
                const uint32_t fo = fold_off(r, c);
                CP_ASYNC16(baseA + fo,            gA + (size_t)r * CDIM + k0 + c * 8);
                CP_ASYNC16(baseA + TILE32_B + fo, gB + (size_t)r * CDIM + k0 + c * 8);
            }
            CP_COMMIT();
        };

        load_stage(0, 0);
        load_stage(1, 1);

        #pragma unroll 1
        for (int ch = 0; ch < nch; ch++) {
            if (ch + 1 < nch) { CP_WAIT(1); }
            else              { CP_WAIT(0); }
            __syncthreads();
            if (ch + 2 < nch) load_stage(ch + 2, (ch + 2) % 3);

            const uint32_t st = sb + (ch % 3) * STAGE16_B;

            uint32_t af[2][4][4], bf[2][4][4];
            #pragma unroll
            for (int kb = 0; kb < 2; kb++) {
                const uint32_t x = (uint32_t)(kb << 5);
                #pragma unroll
                for (int mt = 0; mt < 4; mt++)
                    LDSM_X4(af[kb][mt][0], af[kb][mt][1], af[kb][mt][2], af[kb][mt][3],
                            st + (offA[mt] ^ x));
                #pragma unroll
                for (int nt = 0; nt < 4; nt++)
                    LDSM_X4(bf[kb][nt][0], bf[kb][nt][1], bf[kb][nt][2], bf[kb][nt][3],
                            st + (offB[nt] ^ x));
            }
            #pragma unroll
            for (int kb = 0; kb < 2; kb++)
                #pragma unroll
                for (int mt = 0; mt < 4; mt++)
                    #pragma unroll
                    for (int n8 = 0; n8 < 8; n8++) {
                        const int nt = n8 >> 1, s2 = n8 & 1;
                        MMA_F16(acc[mt][n8], af[kb][mt], bf[kb][nt][s2], bf[kb][nt][s2 + 2]);
                    }
        }

        // Epilogue
        const int quad = lane >> 2;
        const int tq   = (lane & 3) * 2;
        #pragma unroll
        for (int mt = 0; mt < 4; mt++) {
            #pragma unroll
            for (int n8 = 0; n8 < 8; n8++) {
                const int col = n0 + wn + n8 * 8 + tq;
                const int row = m0 + wm + mt * 16 + quad;
                float b0 = bias[col], b1 = bias[col + 1];
                if (QKV) {
                    const int tsel = col / CDIM;
                    const int hd = col % CDIM;
                    const int hh = hd >> 6, d = hd & 63;
                    float z0 = zeta[hd], z1 = zeta[hd + 1];
                    float v0 = (acc[mt][n8][0] + b0) * z0;
                    float v1 = (acc[mt][n8][1] + b1) * z1;
                    float v2 = (acc[mt][n8][2] + b0) * z0;
                    float v3 = (acc[mt][n8][3] + b1) * z1;
                    if (tsel == 0) { v0 *= 0.125f; v1 *= 0.125f; v2 *= 0.125f; v3 *= 0.125f; }
                    __half* dst = (tsel == 0) ? g_q : (tsel == 1) ? g_k : g_v;
                    const int b = row >> 10, n = row & 1023;
                    const size_t idx = (((size_t)(b * HEADS + hh)) << 16) + (size_t)n * 64 + d;
                    *(uint32_t*)(dst + idx)          = pack2h(v0, v1);
                    *(uint32_t*)(dst + idx + 8 * 64) = pack2h(v2, v3);
                } else {
                    float2 v0 = { acc[mt][n8][0] + b0, acc[mt][n8][1] + b1 };
                    float2 v1 = { acc[mt][n8][2] + b0, acc[mt][n8][3] + b1 };
                    *(float2*)(Cout + (size_t)row * N + col)       = v0;
                    *(float2*)(Cout + (size_t)(row + 8) * N + col) = v1;
                }
            }
        }
        __syncthreads();   // protect smem stages before next tile's loads
    }
}

// ---------------------------------------------------------------------------
// Flash attention (fp16 MMA, fp32 accum) — PERSISTENT tile loop.
// 64 q-rows per tile, 128 threads (4 warps x 16 rows), double-buffered K/V.
// ---------------------------------------------------------------------------
#define AT_Q_B    8192
#define AT_KV_B   8192
#define AT_STAGE  (2 * AT_KV_B)
#define AT_SMEM   (AT_Q_B + 2 * AT_STAGE + 1024)
#define AT_NQ     (SEQ / 64)                       // 16
#define AT_NTILES (BATCH * HEADS * AT_NQ)          // 3072

__global__ void __launch_bounds__(128, 2)
attn_hmma_kernel(const unsigned char* __restrict__ mask)
{
    extern __shared__ char sm[];
    const uint32_t sb = smem_u32(sm);
    const uint32_t stage_s = sb + AT_Q_B;
    unsigned char* msk = (unsigned char*)(sm + AT_Q_B + 2 * AT_STAGE);

    const int tid = threadIdx.x, lane = tid & 31, wid = tid >> 5;

    // loop-invariant fragment offsets
    uint32_t offQ[4], offK[4], offV[4];
    {
        const int r = lane & 15, c = lane >> 4;
        #pragma unroll
        for (int kb = 0; kb < 4; kb++) {
            const int row = wid * 16 + r;
            offQ[kb] = row * 128 + (((kb * 2 + c) ^ (row & 7)) << 4);
        }
        #pragma unroll
        for (int kg = 0; kg < 4; kg++) {
            const int row = kg * 16 + r;
            offK[kg] = row * 128 + ((c ^ (row & 7)) << 4);
        }
        const int ttv = lane >> 3;
        const int key0 = (ttv & 1) * 8 + (lane & 7);
        #pragma unroll
        for (int g = 0; g < 4; g++) {
            const int cc = 2 * g + (ttv >> 1);
            offV[g] = AT_KV_B + key0 * 128 + ((cc ^ (key0 & 7)) << 4);
        }
    }

    #pragma unroll 1
    for (int tile = blockIdx.x; tile < AT_NTILES; tile += gridDim.x) {
        const int qt = tile & (AT_NQ - 1);
        const int h  = (tile >> 4) % HEADS;
        const int b  = tile / (AT_NQ * HEADS);
        const int m0 = qt * 64;
        const size_t head_off = ((size_t)(b * HEADS + h)) << 16;

        auto load_kv = [&](int t, int s) {
            const uint32_t base = stage_s + s * AT_STAGE;
            const size_t ko = head_off + (size_t)(t * 64) * 64;
            #pragma unroll
            for (int j = 0; j < 4; j++) {
                const int i = tid + j * 128;
                const int r = i >> 3, c = i & 7;
                const uint32_t soff = base + r * 128 + ((c ^ (r & 7)) << 4);
                CP_ASYNC16(soff,           g_k + ko + (size_t)r * 64 + c * 8);
                CP_ASYNC16(soff + AT_KV_B, g_v + ko + (size_t)r * 64 + c * 8);
            }
            CP_COMMIT();
        };
        load_kv(0, 0);

        const uint32_t mw0 = ((const uint32_t*)(mask + b * SEQ))[tid];
        const uint32_t mw1 = ((const uint32_t*)(mask + b * SEQ))[tid + 128];
        ((uint32_t*)msk)[tid]       = mw0;
        ((uint32_t*)msk)[tid + 128] = mw1;

        {
            const __half* qs = g_q + head_off + (size_t)m0 * 64;
            #pragma unroll
            for (int j = 0; j < 4; j++) {
                const int i = tid + j * 128;
                const int r = i >> 3, c = i & 7;
                const uint32_t sw = r * 128 + ((c ^ (r & 7)) << 4);
                *(uint4*)(sm + sw) = *(const uint4*)(qs + (size_t)r * 64 + c * 8);
            }
        }
        const int anymask = __syncthreads_or((mw0 | mw1) != 0);

        uint32_t qf[4][4];
        #pragma unroll
        for (int kb = 0; kb < 4; kb++)
            LDSM_X4(qf[kb][0], qf[kb][1], qf[kb][2], qf[kb][3], sb + offQ[kb]);

        float mr0 = -1e30f, mr1 = -1e30f, lr0 = 0.f, lr1 = 0.f;
        float oa[8][4];
        #pragma unroll
        for (int i = 0; i < 8; i++)
            #pragma unroll
            for (int j = 0; j < 4; j++) oa[i][j] = 0.f;

        #pragma unroll 1
        for (int t = 0; t < 16; t++) {
            CP_WAIT(0);
            __syncthreads();
            if (t < 15) load_kv(t + 1, (t + 1) & 1);
            const uint32_t st = stage_s + (t & 1) * AT_STAGE;

            float sa[8][4];
            #pragma unroll
            for (int i = 0; i < 8; i++)
                #pragma unroll
                for (int j = 0; j < 4; j++) sa[i][j] = 0.f;

            #pragma unroll
            for (int kb = 0; kb < 4; kb++) {
                const uint32_t x = (uint32_t)(kb << 5);
                uint32_t kf[4][4];
                #pragma unroll
                for (int kg = 0; kg < 4; kg++)
                    LDSM_X4(kf[kg][0], kf[kg][1], kf[kg][2], kf[kg][3], st + (offK[kg] ^ x));
                #pragma unroll
                for (int kg = 0; kg < 4; kg++)
                    #pragma unroll
                    for (int s2 = 0; s2 < 2; s2++)
                        MMA_F16(sa[kg * 2 + s2], qf[kb], kf[kg][s2], kf[kg][s2 + 2]);
            }

            if (anymask) {
                #pragma unroll
                for (int n8 = 0; n8 < 8; n8++) {
                    const int k0 = t * 64 + n8 * 8 + (lane & 3) * 2;
                    if (msk[k0])     { sa[n8][0] = -3e30f; sa[n8][2] = -3e30f; }
                    if (msk[k0 + 1]) { sa[n8][1] = -3e30f; sa[n8][3] = -3e30f; }
                }
            }

            {
                float t0 = sa[0][0], t1 = sa[0][2];
                #pragma unroll
                for (int n8 = 0; n8 < 8; n8++) {
                    t0 = fmaxf(t0, fmaxf(sa[n8][0], sa[n8][1]));
                    t1 = fmaxf(t1, fmaxf(sa[n8][2], sa[n8][3]));
                }
                t0 = fmaxf(t0, __shfl_xor_sync(0xFFFFFFFFu, t0, 1));
                t0 = fmaxf(t0, __shfl_xor_sync(0xFFFFFFFFu, t0, 2));
                t1 = fmaxf(t1, __shfl_xor_sync(0xFFFFFFFFu, t1, 1));
                t1 = fmaxf(t1, __shfl_xor_sync(0xFFFFFFFFu, t1, 2));
                const float mn0 = fmaxf(mr0, t0), mn1 = fmaxf(mr1, t1);
                const float c0 = __expf(mr0 - mn0), c1 = __expf(mr1 - mn1);
                lr0 *= c0; lr1 *= c1;
                mr0 = mn0; mr1 = mn1;

                #pragma unroll
                for (int n8 = 0; n8 < 8; n8++) {
                    const float p0 = __expf(sa[n8][0] - mn0);
                    const float p1 = __expf(sa[n8][1] - mn0);
                    const float p2 = __expf(sa[n8][2] - mn1);
                    const float p3 = __expf(sa[n8][3] - mn1);
                    lr0 += p0 + p1; lr1 += p2 + p3;
                    oa[n8][0] *= c0; oa[n8][1] *= c0;
                    oa[n8][2] *= c1; oa[n8][3] *= c1;
                    sa[n8][0] = p0; sa[n8][1] = p1;
                    sa[n8][2] = p2; sa[n8][3] = p3;
                }
            }

            #pragma unroll
            for (int kb = 0; kb < 4; kb++) {
                uint32_t pf[4];
                pf[0] = pack2h(sa[2 * kb][0],     sa[2 * kb][1]);
                pf[1] = pack2h(sa[2 * kb][2],     sa[2 * kb][3]);
                pf[2] = pack2h(sa[2 * kb + 1][0], sa[2 * kb + 1][1]);
                pf[3] = pack2h(sa[2 * kb + 1][2], sa[2 * kb + 1][3]);

                uint32_t vf[4][4];
                #pragma unroll
                for (int g = 0; g < 4; g++)
                    LDSM_X4_T(vf[g][0], vf[g][1], vf[g][2], vf[g][3],
                              st + offV[g] + kb * 2048);
                #pragma unroll
                for (int g = 0; g < 4; g++)
                    #pragma unroll
                    for (int s2 = 0; s2 < 2; s2++)
                        MMA_F16(oa[g * 2 + s2], pf, vf[g][2 * s2], vf[g][2 * s2 + 1]);
            }
        }

        lr0 += __shfl_xor_sync(0xFFFFFFFFu, lr0, 1);
        lr0 += __shfl_xor_sync(0xFFFFFFFFu, lr0, 2);
        lr1 += __shfl_xor_sync(0xFFFFFFFFu, lr1, 1);
        lr1 += __shfl_xor_sync(0xFFFFFFFFu, lr1, 2);
        const float inv0 = 1.f / lr0, inv1 = 1.f / lr1;

        const int r0 = m0 + wid * 16 + (lane >> 2);
        const int cb = h * 64 + (lane & 3) * 2;
        #pragma unroll
        for (int n8 = 0; n8 < 8; n8++) {
            const int col = cb + n8 * 8;
            const size_t i0 = (size_t)(b * SEQ + r0) * CDIM + col;
            const size_t i1 = i0 + (size_t)8 * CDIM;
            *(uint32_t*)(g_a + i0) = pack2h(oa[n8][0] * inv0, oa[n8][1] * inv0);
            *(uint32_t*)(g_a + i1) = pack2h(oa[n8][2] * inv1, oa[n8][3] * inv1);
        }
        __syncthreads();   // protect smem (Q tile / stages) before next tile
    }
}

// ---------------------------------------------------------------------------
// Launch
// ---------------------------------------------------------------------------
extern "C" void kernel_launch(void* const* d_in, const int* in_sizes, int n_in,
                              void* d_out, int out_size)
{
    (void)in_sizes; (void)n_in; (void)out_size;
    const float* x      = (const float*)d_in[0];
    const float* W_qkv  = (const float*)d_in[1];
    const float* b_qkv  = (const float*)d_in[2];
    const float* zeta   = (const float*)d_in[3];
    const float* W_proj = (const float*)d_in[4];
    const float* b_proj = (const float*)d_in[5];
    const unsigned char* mask = (const unsigned char*)d_in[6];
    float* out = (float*)d_out;

    cudaFuncSetAttribute(gemm_hmma_kernel<true>,
                         cudaFuncAttributeMaxDynamicSharedMemorySize, GEMM_SMEM);
    cudaFuncSetAttribute(gemm_hmma_kernel<false>,
                         cudaFuncAttributeMaxDynamicSharedMemorySize, GEMM_SMEM);
    cudaFuncSetAttribute(attn_hmma_kernel,
                         cudaFuncAttributeMaxDynamicSharedMemorySize, AT_SMEM);

    int nsm = 148;
    cudaDeviceGetAttribute(&nsm, cudaDevAttrMultiProcessorCount, 0);
    const int pgrid = 2 * nsm;   // 2 CTAs/SM resident for all persistent kernels

    convert_all_kernel<<<NB_X + NB_WQ + NB_WP, 256>>>(x, W_qkv, W_proj);
    gemm_hmma_kernel<true><<<pgrid, 128, GEMM_SMEM>>>(b_qkv, zeta, nullptr);
    attn_hmma_kernel<<<pgrid, 128, AT_SMEM>>>(mask);
    gemm_hmma_kernel<false><<<pgrid, 128, GEMM_SMEM>>>(b_proj, nullptr, out);
}

// round 17
// speedup vs baseline: 1.2651x; 1.0696x over previous
#include <cuda_runtime.h>
#include <cuda_fp16.h>
#include <math.h>
#include <stdint.h>

// Problem constants
#define BATCH 16
#define SEQ   1024
#define CDIM  768
#define HEADS 12
#define HDIM  64
#define QKVC  2304
#define MROWS 16384

// ---------------------------------------------------------------------------
// Scratch (__device__ globals; allocation-free rule)
// ---------------------------------------------------------------------------
#define HELEMS ((size_t)BATCH * HEADS * SEQ * HDIM)
__device__ __align__(128) __half g_x [(size_t)MROWS * CDIM];
__device__ __align__(128) __half g_wq[(size_t)QKVC  * CDIM];
__device__ __align__(128) __half g_wp[(size_t)CDIM  * CDIM];
__device__ __align__(128) __half g_q[HELEMS];
__device__ __align__(128) __half g_k[HELEMS];
__device__ __align__(128) __half g_v[HELEMS];
__device__ __align__(128) __half g_a[(size_t)MROWS * CDIM];

// ---------------------------------------------------------------------------
// PTX helpers
// ---------------------------------------------------------------------------
__device__ __forceinline__ uint32_t smem_u32(const void* p) {
    uint32_t a;
    asm("{ .reg .u64 t; cvta.to.shared.u64 t, %1; cvt.u32.u64 %0, t; }" : "=r"(a) : "l"(p));
    return a;
}
#define CP_ASYNC16(dst, src) \
    asm volatile("cp.async.cg.shared.global [%0], [%1], 16;" :: "r"(dst), "l"(src))
#define CP_COMMIT() asm volatile("cp.async.commit_group;" ::: "memory")
#define CP_WAIT(n)  asm volatile("cp.async.wait_group %0;" :: "n"(n) : "memory")

#define LDSM_X4(r0, r1, r2, r3, addr) \
    asm volatile("ldmatrix.sync.aligned.m8n8.x4.shared.b16 {%0,%1,%2,%3}, [%4];" \
        : "=r"(r0), "=r"(r1), "=r"(r2), "=r"(r3) : "r"(addr))
#define LDSM_X4_T(r0, r1, r2, r3, addr) \
    asm volatile("ldmatrix.sync.aligned.m8n8.x4.trans.shared.b16 {%0,%1,%2,%3}, [%4];" \
        : "=r"(r0), "=r"(r1), "=r"(r2), "=r"(r3) : "r"(addr))

#define MMA_F16(d, a, b0r, b1r) \
    asm volatile("mma.sync.aligned.m16n8k16.row.col.f32.f16.f16.f32 " \
        "{%0,%1,%2,%3},{%4,%5,%6,%7},{%8,%9},{%0,%1,%2,%3};" \
        : "+f"((d)[0]), "+f"((d)[1]), "+f"((d)[2]), "+f"((d)[3]) \
        : "r"((a)[0]), "r"((a)[1]), "r"((a)[2]), "r"((a)[3]), "r"(b0r), "r"(b1r))

__device__ __forceinline__ uint32_t pack2h(float a, float b) {
    __half2 h = __floats2half2_rn(a, b);
    return *(uint32_t*)&h;
}

// ---------------------------------------------------------------------------
// Fused conversion kernel (one launch: x->fp16 + both W transposes)
// ---------------------------------------------------------------------------
#define NB_X   (MROWS * CDIM / 4 / 256)                 // 12288
#define NB_WQ  ((QKVC / 32) * (CDIM / 32))              // 1728
#define NB_WP  ((CDIM / 32) * (CDIM / 32))              // 576

__global__ void __launch_bounds__(256)
convert_all_kernel(const float* __restrict__ x,
                   const float* __restrict__ Wq,
                   const float* __restrict__ Wp)
{
    const int bid = blockIdx.x;
    const int tid = threadIdx.x;

    if (bid < NB_X) {
        const int i = bid * 256 + tid;
        float4 v = ((const float4*)x)[i];
        uint2 o;
        o.x = pack2h(v.x, v.y);
        o.y = pack2h(v.z, v.w);
        ((uint2*)g_x)[i] = o;
        return;
    }

    __shared__ float tile[32][33];
    const float* W;
    __half* o;
    int Nd, tb;
    if (bid < NB_X + NB_WQ) { W = Wq; o = g_wq; Nd = QKVC; tb = bid - NB_X; }
    else                    { W = Wp; o = g_wp; Nd = CDIM; tb = bid - NB_X - NB_WQ; }
    const int ntile = Nd / 32;
    const int n0 = (tb % ntile) * 32;
    const int k0 = (tb / ntile) * 32;
    const int tx = tid & 31, ty = tid >> 5;

    #pragma unroll
    for (int j = 0; j < 4; j++)
        tile[ty + j * 8][tx] = W[(size_t)(k0 + ty + j * 8) * Nd + n0 + tx];
    __syncthreads();
    #pragma unroll
    for (int j = 0; j < 4; j++) {
        const int n = n0 + ty + j * 8;
        const int k = k0 + tx;
        o[(size_t)n * CDIM + k] = __float2half(tile[tx][ty + j * 8]);
    }
}

// ---------------------------------------------------------------------------
// HMMA fp16 GEMM (fp32 accumulate). 128x128 CTA tile, BK=32, SIX-stage
// cp.async pipeline with ONE barrier per TWO chunks. 128 threads
// (4 warps, 64x64 warp tile), 2 CTAs/SM.
// ---------------------------------------------------------------------------
#define TILE32_B  8192
#define STAGE16_B (2 * TILE32_B)        // A|B = 16KB
#define GEMM_NSTG 6
#define GEMM_SMEM (GEMM_NSTG * STAGE16_B)   // 98304

__device__ __forceinline__ uint32_t fold_off(int row, int c16) {
    return (uint32_t)((row & 63) * 128 + (((((row >> 6) << 2) + c16) ^ (row & 7)) << 4));
}

template<bool QKV>
__global__ void __launch_bounds__(128, 2)
gemm_hmma_kernel(const float* __restrict__ bias,
                 const float* __restrict__ zeta,
                 float* __restrict__ Cout)
{
    const int N = QKV ? QKVC : CDIM;
    const __half* A = QKV ? g_x  : g_a;
    const __half* B = QKV ? g_wq : g_wp;

    extern __shared__ char smem[];
    const uint32_t sb = smem_u32(smem);
    const int tid  = threadIdx.x;
    const int lane = tid & 31;
    const int wid  = tid >> 5;
    const int wm   = (wid >> 1) * 64;
    const int wn   = (wid & 1) * 64;
    const int m0   = blockIdx.y * 128;
    const int n0   = blockIdx.x * 128;

    const __half* gA = A + (size_t)m0 * CDIM;
    const __half* gB = B + (size_t)n0 * CDIM;

    uint32_t offA[4], offB[4];
    {
        const int r = lane & 15, c = lane >> 4;
        #pragma unroll
        for (int mt = 0; mt < 4; mt++) offA[mt] = fold_off(wm + mt * 16 + r, c);
        #pragma unroll
        for (int nt = 0; nt < 4; nt++) offB[nt] = TILE32_B + fold_off(wn + nt * 16 + r, c);
    }

    float acc[4][8][4];
    #pragma unroll
    for (int a = 0; a < 4; a++)
        #pragma unroll
        for (int b = 0; b < 8; b++)
            #pragma unroll
            for (int c = 0; c < 4; c++) acc[a][b][c] = 0.f;

    auto load_stage = [&](int chunk, int stage) {
        const int k0 = chunk * 32;
        const uint32_t baseA = sb + stage * STAGE16_B;
        #pragma unroll
        for (int j = 0; j < 4; j++) {
            const int i = tid + j * 128;
            const int r = i >> 2;
            const int c = i & 3;
            const uint32_t fo = fold_off(r, c);
            CP_ASYNC16(baseA + fo,            gA + (size_t)r * CDIM + k0 + c * 8);
            CP_ASYNC16(baseA + TILE32_B + fo, gB + (size_t)r * CDIM + k0 + c * 8);
        }
        CP_COMMIT();
    };

    // prologue: 4 chunks in flight
    load_stage(0, 0);
    load_stage(1, 1);
    load_stage(2, 2);
    load_stage(3, 3);

    const int NIT = (CDIM / 32) / 2;   // 12 iterations, 2 chunks each

    #pragma unroll 1
    for (int it = 0; it < NIT; it++) {
        const int c0 = 2 * it;
        if (it + 1 < NIT) { CP_WAIT(2); }   // chunks c0, c0+1 complete
        else              { CP_WAIT(0); }
        __syncthreads();
        // issue chunks c0+4, c0+5 (their stages were consumed in iter it-1)
        if (c0 + 4 < CDIM / 32) load_stage(c0 + 4, (c0 + 4) % GEMM_NSTG);
        if (c0 + 5 < CDIM / 32) load_stage(c0 + 5, (c0 + 5) % GEMM_NSTG);

        #pragma unroll
        for (int ch2 = 0; ch2 < 2; ch2++) {
            const uint32_t st = sb + ((c0 + ch2) % GEMM_NSTG) * STAGE16_B;

            uint32_t af[2][4][4], bf[2][4][4];
            #pragma unroll
            for (int kb = 0; kb < 2; kb++) {
                const uint32_t x = (uint32_t)(kb << 5);
                #pragma unroll
                for (int mt = 0; mt < 4; mt++)
                    LDSM_X4(af[kb][mt][0], af[kb][mt][1], af[kb][mt][2], af[kb][mt][3],
                            st + (offA[mt] ^ x));
                #pragma unroll
                for (int nt = 0; nt < 4; nt++)
                    LDSM_X4(bf[kb][nt][0], bf[kb][nt][1], bf[kb][nt][2], bf[kb][nt][3],
                            st + (offB[nt] ^ x));
            }
            #pragma unroll
            for (int kb = 0; kb < 2; kb++)
                #pragma unroll
                for (int mt = 0; mt < 4; mt++)
                    #pragma unroll
                    for (int n8 = 0; n8 < 8; n8++) {
                        const int nt = n8 >> 1, s2 = n8 & 1;
                        MMA_F16(acc[mt][n8], af[kb][mt], bf[kb][nt][s2], bf[kb][nt][s2 + 2]);
                    }
        }
    }

    // Epilogue
    const int quad = lane >> 2;
    const int tq   = (lane & 3) * 2;
    #pragma unroll
    for (int mt = 0; mt < 4; mt++) {
        #pragma unroll
        for (int n8 = 0; n8 < 8; n8++) {
            const int col = n0 + wn + n8 * 8 + tq;
            const int row = m0 + wm + mt * 16 + quad;
            float b0 = bias[col], b1 = bias[col + 1];
            if (QKV) {
                const int tsel = col / CDIM;
                const int hd = col % CDIM;
                const int hh = hd >> 6, d = hd & 63;
                float z0 = zeta[hd], z1 = zeta[hd + 1];
                float v0 = (acc[mt][n8][0] + b0) * z0;
                float v1 = (acc[mt][n8][1] + b1) * z1;
                float v2 = (acc[mt][n8][2] + b0) * z0;
                float v3 = (acc[mt][n8][3] + b1) * z1;
                if (tsel == 0) { v0 *= 0.125f; v1 *= 0.125f; v2 *= 0.125f; v3 *= 0.125f; }
                __half* dst = (tsel == 0) ? g_q : (tsel == 1) ? g_k : g_v;
                const int b = row >> 10, n = row & 1023;
                const size_t idx = (((size_t)(b * HEADS + hh)) << 16) + (size_t)n * 64 + d;
                *(uint32_t*)(dst + idx)          = pack2h(v0, v1);
                *(uint32_t*)(dst + idx + 8 * 64) = pack2h(v2, v3);
            } else {
                float2 v0 = { acc[mt][n8][0] + b0, acc[mt][n8][1] + b1 };
                float2 v1 = { acc[mt][n8][2] + b0, acc[mt][n8][3] + b1 };
                *(float2*)(Cout + (size_t)row * N + col)       = v0;
                *(float2*)(Cout + (size_t)(row + 8) * N + col) = v1;
            }
        }
    }
}

// ---------------------------------------------------------------------------
// Flash attention on fp16 mma.sync (R14 config — best known). 64 q-rows per
// CTA, 128 threads (4 warps x 16 rows), double-buffered K/V.
// ---------------------------------------------------------------------------
#define AT_Q_B    8192
#define AT_KV_B   8192
#define AT_STAGE  (2 * AT_KV_B)
#define AT_SMEM   (AT_Q_B + 2 * AT_STAGE + 1024)

__global__ void __launch_bounds__(128, 2)
attn_hmma_kernel(const unsigned char* __restrict__ mask)
{
    extern __shared__ char sm[];
    const uint32_t sb = smem_u32(sm);
    const uint32_t stage_s = sb + AT_Q_B;
    unsigned char* msk = (unsigned char*)(sm + AT_Q_B + 2 * AT_STAGE);

    const int tid = threadIdx.x, lane = tid & 31, wid = tid >> 5;
    const int qt = blockIdx.x, h = blockIdx.y, b = blockIdx.z;
    const int m0 = qt * 64;
    const size_t head_off = ((size_t)(b * HEADS + h)) << 16;

    auto load_kv = [&](int t, int s) {
        const uint32_t base = stage_s + s * AT_STAGE;
        const size_t ko = head_off + (size_t)(t * 64) * 64;
        #pragma unroll
        for (int j = 0; j < 4; j++) {
            const int i = tid + j * 128;
            const int r = i >> 3, c = i & 7;
            const uint32_t soff = base + r * 128 + ((c ^ (r & 7)) << 4);
            CP_ASYNC16(soff,           g_k + ko + (size_t)r * 64 + c * 8);
            CP_ASYNC16(soff + AT_KV_B, g_v + ko + (size_t)r * 64 + c * 8);
        }
        CP_COMMIT();
    };
    load_kv(0, 0);

    const uint32_t mw0 = ((const uint32_t*)(mask + b * SEQ))[tid];
    const uint32_t mw1 = ((const uint32_t*)(mask + b * SEQ))[tid + 128];
    ((uint32_t*)msk)[tid]       = mw0;
    ((uint32_t*)msk)[tid + 128] = mw1;

    {
        const __half* qs = g_q + head_off + (size_t)m0 * 64;
        #pragma unroll
        for (int j = 0; j < 4; j++) {
            const int i = tid + j * 128;
            const int r = i >> 3, c = i & 7;
            const uint32_t sw = r * 128 + ((c ^ (r & 7)) << 4);
            *(uint4*)(sm + sw) = *(const uint4*)(qs + (size_t)r * 64 + c * 8);
        }
    }
    const int anymask = __syncthreads_or((mw0 | mw1) != 0);

    uint32_t qf[4][4];
    #pragma unroll
    for (int kb = 0; kb < 4; kb++) {
        const int row = wid * 16 + (lane & 15);
        const int col = kb * 2 + (lane >> 4);
        const uint32_t off = row * 128 + ((col ^ (row & 7)) << 4);
        LDSM_X4(qf[kb][0], qf[kb][1], qf[kb][2], qf[kb][3], sb + off);
    }

    uint32_t offK[4], offV[4];
    {
        const int r = lane & 15, c = lane >> 4;
        #pragma unroll
        for (int kg = 0; kg < 4; kg++) {
            const int row = kg * 16 + r;
            offK[kg] = row * 128 + ((c ^ (row & 7)) << 4);
        }
        const int ttv = lane >> 3;
        const int key0 = (ttv & 1) * 8 + (lane & 7);
        #pragma unroll
        for (int g = 0; g < 4; g++) {
            const int cc = 2 * g + (ttv >> 1);
            offV[g] = AT_KV_B + key0 * 128 + ((cc ^ (key0 & 7)) << 4);
        }
    }

    float mr0 = -1e30f, mr1 = -1e30f, lr0 = 0.f, lr1 = 0.f;
    float oa[8][4];
    #pragma unroll
    for (int i = 0; i < 8; i++)
        #pragma unroll
        for (int j = 0; j < 4; j++) oa[i][j] = 0.f;

    #pragma unroll 1
    for (int t = 0; t < 16; t++) {
        CP_WAIT(0);
        __syncthreads();
        if (t < 15) load_kv(t + 1, (t + 1) & 1);
        const uint32_t st = stage_s + (t & 1) * AT_STAGE;

        float sa[8][4];
        #pragma unroll
        for (int i = 0; i < 8; i++)
            #pragma unroll
            for (int j = 0; j < 4; j++) sa[i][j] = 0.f;

        #pragma unroll
        for (int kb = 0; kb < 4; kb++) {
            const uint32_t x = (uint32_t)(kb << 5);
            uint32_t kf[4][4];
            #pragma unroll
            for (int kg = 0; kg < 4; kg++)
                LDSM_X4(kf[kg][0], kf[kg][1], kf[kg][2], kf[kg][3], st + (offK[kg] ^ x));
            #pragma unroll
            for (int kg = 0; kg < 4; kg++)
                #pragma unroll
                for (int s2 = 0; s2 < 2; s2++)
                    MMA_F16(sa[kg * 2 + s2], qf[kb], kf[kg][s2], kf[kg][s2 + 2]);
        }

        if (anymask) {
            #pragma unroll
            for (int n8 = 0; n8 < 8; n8++) {
                const int k0 = t * 64 + n8 * 8 + (lane & 3) * 2;
                if (msk[k0])     { sa[n8][0] = -3e30f; sa[n8][2] = -3e30f; }
                if (msk[k0 + 1]) { sa[n8][1] = -3e30f; sa[n8][3] = -3e30f; }
            }
        }

        {
            float t0 = sa[0][0], t1 = sa[0][2];
            #pragma unroll
            for (int n8 = 0; n8 < 8; n8++) {
                t0 = fmaxf(t0, fmaxf(sa[n8][0], sa[n8][1]));
                t1 = fmaxf(t1, fmaxf(sa[n8][2], sa[n8][3]));
            }
            t0 = fmaxf(t0, __shfl_xor_sync(0xFFFFFFFFu, t0, 1));
            t0 = fmaxf(t0, __shfl_xor_sync(0xFFFFFFFFu, t0, 2));
            t1 = fmaxf(t1, __shfl_xor_sync(0xFFFFFFFFu, t1, 1));
            t1 = fmaxf(t1, __shfl_xor_sync(0xFFFFFFFFu, t1, 2));
            const float mn0 = fmaxf(mr0, t0), mn1 = fmaxf(mr1, t1);
            const float c0 = __expf(mr0 - mn0), c1 = __expf(mr1 - mn1);
            lr0 *= c0; lr1 *= c1;
            mr0 = mn0; mr1 = mn1;

            #pragma unroll
            for (int n8 = 0; n8 < 8; n8++) {
                const float p0 = __expf(sa[n8][0] - mn0);
                const float p1 = __expf(sa[n8][1] - mn0);
                const float p2 = __expf(sa[n8][2] - mn1);
                const float p3 = __expf(sa[n8][3] - mn1);
                lr0 += p0 + p1; lr1 += p2 + p3;
                oa[n8][0] *= c0; oa[n8][1] *= c0;
                oa[n8][2] *= c1; oa[n8][3] *= c1;
                sa[n8][0] = p0; sa[n8][1] = p1;
                sa[n8][2] = p2; sa[n8][3] = p3;
            }
        }

        #pragma unroll
        for (int kb = 0; kb < 4; kb++) {
            uint32_t pf[4];
            pf[0] = pack2h(sa[2 * kb][0],     sa[2 * kb][1]);
            pf[1] = pack2h(sa[2 * kb][2],     sa[2 * kb][3]);
            pf[2] = pack2h(sa[2 * kb + 1][0], sa[2 * kb + 1][1]);
            pf[3] = pack2h(sa[2 * kb + 1][2], sa[2 * kb + 1][3]);

            uint32_t vf[4][4];
            #pragma unroll
            for (int g = 0; g < 4; g++)
                LDSM_X4_T(vf[g][0], vf[g][1], vf[g][2], vf[g][3],
                          st + offV[g] + kb * 2048);
            #pragma unroll
            for (int g = 0; g < 4; g++)
                #pragma unroll
                for (int s2 = 0; s2 < 2; s2++)
                    MMA_F16(oa[g * 2 + s2], pf, vf[g][2 * s2], vf[g][2 * s2 + 1]);
        }
    }

    lr0 += __shfl_xor_sync(0xFFFFFFFFu, lr0, 1);
    lr0 += __shfl_xor_sync(0xFFFFFFFFu, lr0, 2);
    lr1 += __shfl_xor_sync(0xFFFFFFFFu, lr1, 1);
    lr1 += __shfl_xor_sync(0xFFFFFFFFu, lr1, 2);
    const float inv0 = 1.f / lr0, inv1 = 1.f / lr1;

    const int r0 = m0 + wid * 16 + (lane >> 2);
    const int cb = h * 64 + (lane & 3) * 2;
    #pragma unroll
    for (int n8 = 0; n8 < 8; n8++) {
        const int col = cb + n8 * 8;
        const size_t i0 = (size_t)(b * SEQ + r0) * CDIM + col;
        const size_t i1 = i0 + (size_t)8 * CDIM;
        *(uint32_t*)(g_a + i0) = pack2h(oa[n8][0] * inv0, oa[n8][1] * inv0);
        *(uint32_t*)(g_a + i1) = pack2h(oa[n8][2] * inv1, oa[n8][3] * inv1);
    }
}

// ---------------------------------------------------------------------------
// Launch
// ---------------------------------------------------------------------------
extern "C" void kernel_launch(void* const* d_in, const int* in_sizes, int n_in,
                              void* d_out, int out_size)
{
    (void)in_sizes; (void)n_in; (void)out_size;
    const float* x      = (const float*)d_in[0];
    const float* W_qkv  = (const float*)d_in[1];
    const float* b_qkv  = (const float*)d_in[2];
    const float* zeta   = (const float*)d_in[3];
    const float* W_proj = (const float*)d_in[4];
    const float* b_proj = (const float*)d_in[5];
    const unsigned char* mask = (const unsigned char*)d_in[6];
    float* out = (float*)d_out;

    cudaFuncSetAttribute(gemm_hmma_kernel<true>,
                         cudaFuncAttributeMaxDynamicSharedMemorySize, GEMM_SMEM);
    cudaFuncSetAttribute(gemm_hmma_kernel<false>,
                         cudaFuncAttributeMaxDynamicSharedMemorySize, GEMM_SMEM);
    cudaFuncSetAttribute(attn_hmma_kernel,
                         cudaFuncAttributeMaxDynamicSharedMemorySize, AT_SMEM);

    convert_all_kernel<<<NB_X + NB_WQ + NB_WP, 256>>>(x, W_qkv, W_proj);
    gemm_hmma_kernel<true><<<dim3(QKVC / 128, MROWS / 128), 128, GEMM_SMEM>>>(b_qkv, zeta, nullptr);
    attn_hmma_kernel<<<dim3(SEQ / 64, HEADS, BATCH), 128, AT_SMEM>>>(mask);
    gemm_hmma_kernel<false><<<dim3(CDIM / 128, MROWS / 128), 128, GEMM_SMEM>>>(b_proj, nullptr, out);
}